// round 9
// baseline (speedup 1.0000x reference)
#include <cuda_runtime.h>
#include <cuda_bf16.h>
#include <cstdint>

// MaxUnpooling2DMod: out[b, y(idx), x(idx), c] += in[b,h,w,c]
//   in  [8,128,128,64] -> 2^23 floats, out [8,256,256,64] -> 2^25 floats
// decode: out_off = (b << 22) + (idx & ~63) + (lin & 63)
//
// PDL skip-chain (R8 structure): z0,s0,z1,s1,...
//   z_b: zero slab b, no wait, trigger after stores.
//   s_b: trigger at entry (releases z_{b+1} immediately), issue ALL loads,
//        wait (-> z_b completion only), fire 8 REDGs.
// R9 change: fat threads — 8 elems/thread in scatter (4x LDG.128 in flight,
// dense REDG stream), 8 float4/thread in zero. 512-block grids, sub-one-wave.

static constexpr int BLOCK = 256;
static constexpr int GRID  = 512;
static constexpr int THREADS = GRID * BLOCK;              // 131072

// ---- zero kernel: one 16.8 MB slab ----
static constexpr int SLAB_F4    = (1 << 22) / 4;          // 1,048,576 float4
static constexpr int ZERO_PER_T = SLAB_F4 / THREADS;      // 8

__global__ void __launch_bounds__(BLOCK)
zero_slab_kernel(float* __restrict__ out, int slab)
{
    const int t = blockIdx.x * BLOCK + threadIdx.x;
    float4* o4 = reinterpret_cast<float4*>(out) + (size_t)slab * SLAB_F4;
    const float4 z = make_float4(0.f, 0.f, 0.f, 0.f);
    #pragma unroll
    for (int j = 0; j < ZERO_PER_T; j++)
        o4[t + j * THREADS] = z;                          // default policy: stay dirty in L2
    asm volatile("griddepcontrol.launch_dependents;" ::: "memory");
}

// ---- scatter kernel: batch b -> slab b, 8 elems/thread ----
__global__ void __launch_bounds__(BLOCK)
scatter_kernel(const float* __restrict__ in,
               const int*   __restrict__ idx,
               float*       __restrict__ out,
               int b)
{
    // Release z_{b+1} (disjoint slab) immediately.
    asm volatile("griddepcontrol.launch_dependents;" ::: "memory");

    const int t  = blockIdx.x * BLOCK + threadIdx.x;      // 131072 threads
    const int e0 = (b << 20) + (t << 3);                  // 8 consecutive elems

    // 4 independent 16B streaming loads in flight before the wait.
    const float4* in4  = reinterpret_cast<const float4*>(in)  + (e0 >> 2);
    const int4*   idx4 = reinterpret_cast<const int4*>(idx)   + (e0 >> 2);
    const float4 v0  = __ldcs(in4 + 0);
    const float4 v1  = __ldcs(in4 + 1);
    const int4   id0 = __ldcs(idx4 + 0);
    const int4   id1 = __ldcs(idx4 + 1);

    // Wait for z_b (immediate predecessor) completion: slab b zeroed+visible.
    asm volatile("griddepcontrol.wait;" ::: "memory");

    float* o = out + (b << 22);
    const int c0 = e0 & 63;                               // e0 multiple of 8
    atomicAdd(o + (id0.x & ~63) + (c0 + 0), v0.x);
    atomicAdd(o + (id0.y & ~63) + (c0 + 1), v0.y);
    atomicAdd(o + (id0.z & ~63) + (c0 + 2), v0.z);
    atomicAdd(o + (id0.w & ~63) + (c0 + 3), v0.w);
    atomicAdd(o + (id1.x & ~63) + (c0 + 4), v1.x);
    atomicAdd(o + (id1.y & ~63) + (c0 + 5), v1.y);
    atomicAdd(o + (id1.z & ~63) + (c0 + 6), v1.z);
    atomicAdd(o + (id1.w & ~63) + (c0 + 7), v1.w);
}

extern "C" void kernel_launch(void* const* d_in, const int* in_sizes, int n_in,
                              void* d_out, int out_size)
{
    const float* in  = (const float*)d_in[0];
    const int*   idx = (const int*)d_in[1];
    float*       out = (float*)d_out;

    cudaLaunchAttribute attrs[1];
    attrs[0].id = cudaLaunchAttributeProgrammaticStreamSerialization;
    attrs[0].val.programmaticStreamSerializationAllowed = 1;

    cudaLaunchConfig_t cfg = {};
    cfg.gridDim  = dim3(GRID, 1, 1);
    cfg.blockDim = dim3(BLOCK, 1, 1);
    cfg.stream   = 0;

    for (int b = 0; b < 8; b++) {
        cfg.attrs    = (b == 0) ? nullptr : attrs;        // z0 has no predecessor
        cfg.numAttrs = (b == 0) ? 0 : 1;
        cudaLaunchKernelEx(&cfg, zero_slab_kernel, out, b);

        cfg.attrs = attrs;  cfg.numAttrs = 1;
        cudaLaunchKernelEx(&cfg, scatter_kernel, in, idx, out, b);
    }
}